// round 1
// baseline (speedup 1.0000x reference)
#include <cuda_runtime.h>
#include <cstdint>

// RoIAlign, matching the JAX reference exactly.
// features: (B=2, C=256, H=200, W=200) f32 NCHW
// rois:     (N=512, 5) f32  [batch_idx, x1, y1, x2, y2] (image coords)
// out:      (N, C, 7, 7) f32
// SPATIAL_SCALE = 0.0625, SAMPLING_RATIO = 2, POOLED = 7x7

#define POOLED 7
#define SCALE 0.0625f
#define CH 256
#define FH 200
#define FW 200

__global__ void roi_align_kernel(const float* __restrict__ features,
                                 const float* __restrict__ rois,
                                 float* __restrict__ out,
                                 int total)
{
    int idx = blockIdx.x * blockDim.x + threadIdx.x;
    if (idx >= total) return;

    int pw = idx % POOLED;
    int ph = (idx / POOLED) % POOLED;
    int c  = (idx / (POOLED * POOLED)) % CH;
    int n  = idx / (POOLED * POOLED * CH);

    const float* roi = rois + n * 5;
    int   b  = (int)__ldg(&roi[0]);
    float x1 = __ldg(&roi[1]) * SCALE;
    float y1 = __ldg(&roi[2]) * SCALE;
    float x2 = __ldg(&roi[3]) * SCALE;
    float y2 = __ldg(&roi[4]) * SCALE;

    float roi_w = fmaxf(x2 - x1, 1.0f);
    float roi_h = fmaxf(y2 - y1, 1.0f);
    float bin_w = roi_w * (1.0f / POOLED);
    float bin_h = roi_h * (1.0f / POOLED);

    const float* __restrict__ fptr =
        features + ((size_t)b * CH + (size_t)c) * (FH * FW);

    // Precompute x-axis interpolation for the 2 sample columns of this bin.
    int   xl[2], xh[2];
    float fx[2];
    bool  vx[2];
#pragma unroll
    for (int sx = 0; sx < 2; sx++) {
        float x = fmaf((float)pw + (sx + 0.5f) * 0.5f, bin_w, x1);
        vx[sx] = (x >= -1.0f) && (x <= (float)FW);
        float cx = fmaxf(x, 0.0f);
        int lo = min((int)floorf(cx), FW - 1);
        xl[sx] = lo;
        xh[sx] = min(lo + 1, FW - 1);
        fx[sx] = (lo >= FW - 1) ? 0.0f : (cx - (float)lo);
    }

    float acc = 0.0f;
#pragma unroll
    for (int sy = 0; sy < 2; sy++) {
        float y = fmaf((float)ph + (sy + 0.5f) * 0.5f, bin_h, y1);
        bool vy = (y >= -1.0f) && (y <= (float)FH);
        float cy = fmaxf(y, 0.0f);
        int yl = min((int)floorf(cy), FH - 1);
        int yh = min(yl + 1, FH - 1);
        float fyv = (yl >= FH - 1) ? 0.0f : (cy - (float)yl);
        float hy = 1.0f - fyv;

        const float* row_l = fptr + yl * FW;
        const float* row_h = fptr + yh * FW;

#pragma unroll
        for (int sx = 0; sx < 2; sx++) {
            if (!(vy && vx[sx])) continue;
            float hx = 1.0f - fx[sx];
            float lx = fx[sx];
            float v00 = __ldg(row_l + xl[sx]);
            float v01 = __ldg(row_l + xh[sx]);
            float v10 = __ldg(row_h + xl[sx]);
            float v11 = __ldg(row_h + xh[sx]);
            float top = fmaf(lx, v01, hx * v00);
            float bot = fmaf(lx, v11, hx * v10);
            acc = fmaf(hy, top, fmaf(fyv, bot, acc));
        }
    }

    out[idx] = acc * 0.25f;  // mean over S*S = 4 samples
}

extern "C" void kernel_launch(void* const* d_in, const int* in_sizes, int n_in,
                              void* d_out, int out_size)
{
    const float* features = (const float*)d_in[0];
    const float* rois     = (const float*)d_in[1];
    float*       out      = (float*)d_out;

    int n_rois = in_sizes[1] / 5;           // 512
    int total  = n_rois * CH * POOLED * POOLED;  // == out_size

    int threads = 256;
    int blocks  = (total + threads - 1) / threads;
    roi_align_kernel<<<blocks, threads>>>(features, rois, out, total);
}